// round 3
// baseline (speedup 1.0000x reference)
#include <cuda_runtime.h>
#include <math.h>

// ============================================================================
// FullyConnectedTensorProduct: (0e+1o+2e)x128  ⊗  (0e+1o+2e)x1  ->  (0e+1o+2e)x128
// 11 paths, uvw weights 128x1x128 each.
//
// Stage 0 (init kernel, 11 blocks): compute e3nn real-basis Wigner 3j for each
//   path in double precision on device, normalized + path-weight scaled,
//   emitted as a sparse entry list grouped by the l1-component index i.
// Stage 1 (main kernel): t[n,u,kc] = sum_ij C[ijk] x1[n,u,i] x2[n,j]  (smem)
// Stage 2 (main kernel): out[n,w,k] = sum_u W_p[u,w] t[n,u,kc]  (fp32 FFMA)
// ============================================================================

#define NPATH 11
#define TILE_N 4
#define NKC 35            // total t columns: sum over paths of (2*lo+1)

struct __align__(16) Ent { float v; int i; int j; int k; };

__device__ Ent g_ent[NPATH][128];
__device__ int g_icnt[NPATH][5];

__constant__ int dL1[NPATH]  = {0,0,0,1,1,1,1,2,2,2,2};
__constant__ int dL2[NPATH]  = {0,1,2,0,1,1,2,0,1,2,2};
__constant__ int dLO[NPATH]  = {0,1,2,1,0,2,1,2,1,0,2};
__constant__ int dSEG2[3]    = {0,1,4};

// ---------------------------------------------------------------------------
// SU(2) Clebsch-Gordan (integer l), exactly mirroring the reference
// ---------------------------------------------------------------------------
__device__ double su2_cg(int j1,int m1,int j2,int m2,int j3,int m3){
    if (m3 != m1 + m2) return 0.0;
    int vmin = max(max(-j1 + j2 + m3, -j1 + m1), 0);
    int vmax = min(min(j2 + j3 + m1, j3 - j1 + j2), j3 + m3);
    if (vmax < vmin) return 0.0;
    const double F[8] = {1.0,1.0,2.0,6.0,24.0,120.0,720.0,5040.0};
    double pref = (2.0*j3 + 1.0) *
        (F[j3+j1-j2]*F[j3-j1+j2]*F[j1+j2-j3]*F[j3+m3]*F[j3-m3]) /
        (F[j1+j2+j3+1]*F[j1-m1]*F[j1+m1]*F[j2-m2]*F[j2+m2]);
    double S = 0.0;
    for (int v = vmin; v <= vmax; ++v) {
        double sgn = ((v + j2 + m2) & 1) ? -1.0 : 1.0;
        S += sgn * (F[j2+j3+m1-v]*F[j1-m1+v]) /
             (F[v]*F[j3-j1+j2-v]*F[j3+m3-v]*F[v+j1-j2-m3]);
    }
    return sqrt(pref) * S;
}

// real->complex change of basis q(l), times (-1j)^l   (q[row][col][re/im])
__device__ void fillQ(int l, double (*q)[2]) {
    const int n = 2*l + 1;
    const double ISQ2 = 0.7071067811865475244;
    for (int i = 0; i < 25; ++i) { q[i][0] = 0.0; q[i][1] = 0.0; }
    for (int m = -l; m < 0; ++m) {
        int row = l + m;
        q[row*n + (l - m)][0] =  ISQ2;   // q[l+m, l+|m|] = 1/sqrt2
        q[row*n + (l + m)][1] = -ISQ2;   // q[l+m, l-|m|] = -i/sqrt2
    }
    q[l*n + l][0] = 1.0;
    for (int m = 1; m <= l; ++m) {
        int row = l + m;
        double s = (m & 1) ? -1.0 : 1.0;
        q[row*n + (l + m)][0] = s * ISQ2;    // (-1)^m/sqrt2
        q[row*n + (l - m)][1] = s * ISQ2;    // i*(-1)^m/sqrt2
    }
    // multiply by (-i)^l
    if (l == 1) {
        for (int i = 0; i < 9; ++i) {
            double r = q[i][0], im = q[i][1];
            q[i][0] = im; q[i][1] = -r;      // *( -i )
        }
    } else if (l == 2) {
        for (int i = 0; i < 25; ++i) { q[i][0] = -q[i][0]; q[i][1] = -q[i][1]; }
    }
}

// ---------------------------------------------------------------------------
// Init kernel: one block per path. Builds the scaled sparse W3J entry lists.
// ---------------------------------------------------------------------------
__global__ void w3j_init_kernel() {
    __shared__ double sC[125];
    __shared__ double sQ1[25][2], sQ2[25][2], sQ3[25][2];
    __shared__ double sXr[125], sXi[125];

    const int p   = blockIdx.x;
    const int tid = threadIdx.x;
    const int l1 = dL1[p], l2 = dL2[p], l3 = dLO[p];
    const int n1 = 2*l1+1, n2 = 2*l2+1, n3 = 2*l3+1;

    for (int i = tid; i < 125; i += blockDim.x) sC[i] = 0.0;
    if (tid == 0) { fillQ(l1, sQ1); fillQ(l2, sQ2); fillQ(l3, sQ3); }
    __syncthreads();

    for (int idx = tid; idx < n1*n2; idx += blockDim.x) {
        int m1 = idx / n2 - l1;
        int m2 = idx % n2 - l2;
        int m3 = m1 + m2;
        if (abs(m3) <= l3)
            sC[idx*n3 + (m3 + l3)] = su2_cg(l1, m1, l2, m2, l3, m3);
    }
    __syncthreads();

    // X[j,l,m] = sum_{i,k,n} Q1[i][j] Q2[k][l] conj(Q3[n][m]) C[i][k][n]
    for (int idx = tid; idx < n1*n2*n3; idx += blockDim.x) {
        int j = idx / (n2*n3);
        int l = (idx / n3) % n2;
        int m = idx % n3;
        double xr = 0.0, xi = 0.0;
        for (int i = 0; i < n1; ++i)
            for (int k = 0; k < n2; ++k)
                for (int n = 0; n < n3; ++n) {
                    double c = sC[(i*n2 + k)*n3 + n];
                    if (c == 0.0) continue;
                    double ar = sQ1[i*n1 + j][0], ai = sQ1[i*n1 + j][1];
                    double br = sQ2[k*n2 + l][0], bi = sQ2[k*n2 + l][1];
                    double t1r = ar*br - ai*bi, t1i = ar*bi + ai*br;
                    double cr = sQ3[n*n3 + m][0], ci = -sQ3[n*n3 + m][1];
                    double t2r = t1r*cr - t1i*ci, t2i = t1r*ci + t1i*cr;
                    xr += c * t2r; xi += c * t2i;
                }
        sXr[idx] = xr; sXi[idx] = xi;
    }
    __syncthreads();

    if (tid == 0) {
        const int tot = n1*n2*n3;
        double nr = 0.0, ni = 0.0;
        for (int i = 0; i < tot; ++i) { nr += sXr[i]*sXr[i]; ni += sXi[i]*sXi[i]; }
        const double* src = (nr >= ni) ? sXr : sXi;
        double norm = sqrt((nr >= ni) ? nr : ni);
        // path_normalization='element': PW = sqrt((2lo+1)/FAN), FAN = 128*paths_to_lo
        double fan = (l3 == 0) ? 384.0 : 512.0;
        double scale = sqrt((2.0*l3 + 1.0) / fan) / norm;

        int cnt = 0;
        int icnt[5] = {0,0,0,0,0};
        for (int i = 0; i < n1; ++i)
            for (int jj = 0; jj < n2; ++jj)
                for (int kk = 0; kk < n3; ++kk) {
                    double v = src[(i*n2 + jj)*n3 + kk] * scale;
                    if (fabs(v) > 1e-10) {
                        Ent e; e.v = (float)v; e.i = i; e.j = dSEG2[l2] + jj; e.k = kk;
                        g_ent[p][cnt++] = e;
                        icnt[i]++;
                    }
                }
        for (int i = 0; i < 5; ++i) g_icnt[p][i] = icnt[i];
    }
}

// ---------------------------------------------------------------------------
// Main kernel: TILE_N=4 rows per block, 128 threads.
// ---------------------------------------------------------------------------
__global__ __launch_bounds__(128)
void fctp_kernel(const float* __restrict__ x1,
                 const float* __restrict__ x2,
                 const float* __restrict__ wgt,
                 float* __restrict__ out,
                 int N)
{
    extern __shared__ float sh[];
    float* t_s  = sh;                         // [35][128][4]
    float* x2s  = sh + NKC*128*TILE_N;        // [4][9]

    const int n0 = blockIdx.x * TILE_N;
    if (n0 >= N) return;
    const int tid = threadIdx.x;
    const int nv  = min(TILE_N, N - n0);

    // stage x2 tile
    if (tid < TILE_N*9) {
        int r = tid / 9, c = tid % 9;
        int n = min(n0 + r, N - 1);
        x2s[r*9 + c] = x2[n*9 + c];
    }
    __syncthreads();

    // ---------------- Stage 1: t[kc][u][nn] -------------------------------
    {
        constexpr int L1[11]  = {0,0,0,1,1,1,1,2,2,2,2};
        constexpr int LO[11]  = {0,1,2,1,0,2,1,2,1,0,2};
        constexpr int TKO[11] = {0,1,4,9,12,13,18,21,26,29,30};
        constexpr int SEG1[3] = {0,128,512};

        const int u = tid;
        for (int nn = 0; nn < TILE_N; ++nn) {
            const int n = min(n0 + nn, N - 1);
            const float* __restrict__ row = x1 + (long)n * 1152;
            const float* x2r = x2s + nn*9;
            #pragma unroll
            for (int p = 0; p < 11; ++p) {
                const int l1 = L1[p], lo = LO[p];
                const int d1 = 2*l1 + 1, nk = 2*lo + 1, tko = TKO[p];
                const float* base = row + SEG1[l1] + u*d1;
                float acc[5] = {0.f,0.f,0.f,0.f,0.f};
                int eidx = 0;
                #pragma unroll
                for (int i = 0; i < 5; ++i) {
                    if (i < d1) {
                        const float xv = __ldg(base + i);
                        const int ci = g_icnt[p][i];
                        for (int c = 0; c < ci; ++c, ++eidx) {
                            const Ent en = g_ent[p][eidx];
                            const float prod = en.v * xv * x2r[en.j];
                            #pragma unroll
                            for (int kk = 0; kk < 5; ++kk)
                                if (kk < nk) acc[kk] += (en.k == kk) ? prod : 0.0f;
                        }
                    }
                }
                #pragma unroll
                for (int kk = 0; kk < 5; ++kk)
                    if (kk < nk) t_s[(tko + kk)*(128*TILE_N) + u*TILE_N + nn] = acc[kk];
            }
        }
    }
    __syncthreads();

    // ---------------- Stage 2: out = W^T @ t ------------------------------
    const int w = tid;
    const float4* __restrict__ t4 = (const float4*)t_s;   // [35][128]

    // lo = 0 : paths 0,4,9  (t cols 0,12,29), K = 384
    {
        constexpr int PP[3] = {0,4,9};
        constexpr int TT[3] = {0,12,29};
        float a[4] = {0.f,0.f,0.f,0.f};
        #pragma unroll
        for (int pi = 0; pi < 3; ++pi) {
            const float* __restrict__ Wp = wgt + PP[pi]*16384 + w;
            const float4* tc = t4 + TT[pi]*128;
            #pragma unroll 8
            for (int u = 0; u < 128; ++u) {
                float wv = __ldg(Wp + u*128);
                float4 tv = tc[u];
                a[0] += wv*tv.x; a[1] += wv*tv.y; a[2] += wv*tv.z; a[3] += wv*tv.w;
            }
        }
        #pragma unroll
        for (int nn = 0; nn < TILE_N; ++nn)
            if (nn < nv) out[(long)(n0 + nn)*1152 + w] = a[nn];
    }

    // lo = 1 : paths 1,3,6,8 (t cols 1,9,18,26), 3 components
    {
        constexpr int PP[4] = {1,3,6,8};
        constexpr int TT[4] = {1,9,18,26};
        float a[3][4] = {};
        #pragma unroll
        for (int pi = 0; pi < 4; ++pi) {
            const float* __restrict__ Wp = wgt + PP[pi]*16384 + w;
            #pragma unroll 8
            for (int u = 0; u < 128; ++u) {
                float wv = __ldg(Wp + u*128);
                #pragma unroll
                for (int k = 0; k < 3; ++k) {
                    float4 tv = t4[(TT[pi] + k)*128 + u];
                    a[k][0] += wv*tv.x; a[k][1] += wv*tv.y;
                    a[k][2] += wv*tv.z; a[k][3] += wv*tv.w;
                }
            }
        }
        #pragma unroll
        for (int nn = 0; nn < TILE_N; ++nn)
            if (nn < nv) {
                long ob = (long)(n0 + nn)*1152 + 128 + w*3;
                #pragma unroll
                for (int k = 0; k < 3; ++k) out[ob + k] = a[k][nn];
            }
    }

    // lo = 2 : paths 2,5,7,10 (t cols 4,13,21,30), 5 components
    {
        constexpr int PP[4] = {2,5,7,10};
        constexpr int TT[4] = {4,13,21,30};
        float a[5][4] = {};
        #pragma unroll
        for (int pi = 0; pi < 4; ++pi) {
            const float* __restrict__ Wp = wgt + PP[pi]*16384 + w;
            #pragma unroll 8
            for (int u = 0; u < 128; ++u) {
                float wv = __ldg(Wp + u*128);
                #pragma unroll
                for (int k = 0; k < 5; ++k) {
                    float4 tv = t4[(TT[pi] + k)*128 + u];
                    a[k][0] += wv*tv.x; a[k][1] += wv*tv.y;
                    a[k][2] += wv*tv.z; a[k][3] += wv*tv.w;
                }
            }
        }
        #pragma unroll
        for (int nn = 0; nn < TILE_N; ++nn)
            if (nn < nv) {
                long ob = (long)(n0 + nn)*1152 + 512 + w*5;
                #pragma unroll
                for (int k = 0; k < 5; ++k) out[ob + k] = a[k][nn];
            }
    }
}

// ---------------------------------------------------------------------------
extern "C" void kernel_launch(void* const* d_in, const int* in_sizes, int n_in,
                              void* d_out, int out_size)
{
    const float* x1  = (const float*)d_in[0];
    const float* x2  = (const float*)d_in[1];
    const float* wgt = (const float*)d_in[2];
    float* out = (float*)d_out;

    const int N = in_sizes[0] / 1152;
    if (N <= 0) return;

    const int smem_bytes = (NKC*128*TILE_N + TILE_N*9) * (int)sizeof(float);
    cudaFuncSetAttribute(fctp_kernel, cudaFuncAttributeMaxDynamicSharedMemorySize,
                         smem_bytes);

    w3j_init_kernel<<<NPATH, 128>>>();
    const int grid = (N + TILE_N - 1) / TILE_N;
    fctp_kernel<<<grid, 128, smem_bytes>>>(x1, x2, wgt, out, N);
}

// round 4
// speedup vs baseline: 1.4560x; 1.4560x over previous
#include <cuda_runtime.h>
#include <math.h>

// ============================================================================
// FullyConnectedTensorProduct: (0e+1o+2e)x128  ⊗  (0e+1o+2e)x1  ->  (0e+1o+2e)x128
// 11 paths, uvw weights 128x1x128 each.
//
// Stage 0 (init kernel): device-side e3nn Wigner-3j (fp64), scaled, sparse.
// Stage 1: t[kc][u][nn] in smem (scalar fp32, split by n-halves across warps)
// Stage 2: out = W^T t via packed fma.rn.f32x2; warps specialized by lo-group.
// ============================================================================

#define NPATH 11
#define TILE_N 4
#define NKC 35            // total t columns: sum over paths of (2*lo+1)

struct __align__(16) Ent { float v; int i; int j; int k; };

__device__ Ent g_ent[NPATH][128];
__device__ int g_icnt[NPATH][5];

__constant__ int dL1[NPATH]  = {0,0,0,1,1,1,1,2,2,2,2};
__constant__ int dL2[NPATH]  = {0,1,2,0,1,1,2,0,1,2,2};
__constant__ int dLO[NPATH]  = {0,1,2,1,0,2,1,2,1,0,2};
__constant__ int dSEG2[3]    = {0,1,4};

// ---------------------------------------------------------------------------
// SU(2) Clebsch-Gordan (integer l), exactly mirroring the reference
// ---------------------------------------------------------------------------
__device__ double su2_cg(int j1,int m1,int j2,int m2,int j3,int m3){
    if (m3 != m1 + m2) return 0.0;
    int vmin = max(max(-j1 + j2 + m3, -j1 + m1), 0);
    int vmax = min(min(j2 + j3 + m1, j3 - j1 + j2), j3 + m3);
    if (vmax < vmin) return 0.0;
    const double F[8] = {1.0,1.0,2.0,6.0,24.0,120.0,720.0,5040.0};
    double pref = (2.0*j3 + 1.0) *
        (F[j3+j1-j2]*F[j3-j1+j2]*F[j1+j2-j3]*F[j3+m3]*F[j3-m3]) /
        (F[j1+j2+j3+1]*F[j1-m1]*F[j1+m1]*F[j2-m2]*F[j2+m2]);
    double S = 0.0;
    for (int v = vmin; v <= vmax; ++v) {
        double sgn = ((v + j2 + m2) & 1) ? -1.0 : 1.0;
        S += sgn * (F[j2+j3+m1-v]*F[j1-m1+v]) /
             (F[v]*F[j3-j1+j2-v]*F[j3+m3-v]*F[v+j1-j2-m3]);
    }
    return sqrt(pref) * S;
}

// real->complex change of basis q(l), times (-1j)^l   (q[row][col][re/im])
__device__ void fillQ(int l, double (*q)[2]) {
    const int n = 2*l + 1;
    const double ISQ2 = 0.7071067811865475244;
    for (int i = 0; i < 25; ++i) { q[i][0] = 0.0; q[i][1] = 0.0; }
    for (int m = -l; m < 0; ++m) {
        int row = l + m;
        q[row*n + (l - m)][0] =  ISQ2;
        q[row*n + (l + m)][1] = -ISQ2;
    }
    q[l*n + l][0] = 1.0;
    for (int m = 1; m <= l; ++m) {
        int row = l + m;
        double s = (m & 1) ? -1.0 : 1.0;
        q[row*n + (l + m)][0] = s * ISQ2;
        q[row*n + (l - m)][1] = s * ISQ2;
    }
    if (l == 1) {
        for (int i = 0; i < 9; ++i) {
            double r = q[i][0], im = q[i][1];
            q[i][0] = im; q[i][1] = -r;
        }
    } else if (l == 2) {
        for (int i = 0; i < 25; ++i) { q[i][0] = -q[i][0]; q[i][1] = -q[i][1]; }
    }
}

// ---------------------------------------------------------------------------
// Init kernel: one block per path. Builds the scaled sparse W3J entry lists.
// ---------------------------------------------------------------------------
__global__ void w3j_init_kernel() {
    __shared__ double sC[125];
    __shared__ double sQ1[25][2], sQ2[25][2], sQ3[25][2];
    __shared__ double sXr[125], sXi[125];

    const int p   = blockIdx.x;
    const int tid = threadIdx.x;
    const int l1 = dL1[p], l2 = dL2[p], l3 = dLO[p];
    const int n1 = 2*l1+1, n2 = 2*l2+1, n3 = 2*l3+1;

    for (int i = tid; i < 125; i += blockDim.x) sC[i] = 0.0;
    if (tid == 0) { fillQ(l1, sQ1); fillQ(l2, sQ2); fillQ(l3, sQ3); }
    __syncthreads();

    for (int idx = tid; idx < n1*n2; idx += blockDim.x) {
        int m1 = idx / n2 - l1;
        int m2 = idx % n2 - l2;
        int m3 = m1 + m2;
        if (abs(m3) <= l3)
            sC[idx*n3 + (m3 + l3)] = su2_cg(l1, m1, l2, m2, l3, m3);
    }
    __syncthreads();

    for (int idx = tid; idx < n1*n2*n3; idx += blockDim.x) {
        int j = idx / (n2*n3);
        int l = (idx / n3) % n2;
        int m = idx % n3;
        double xr = 0.0, xi = 0.0;
        for (int i = 0; i < n1; ++i)
            for (int k = 0; k < n2; ++k)
                for (int n = 0; n < n3; ++n) {
                    double c = sC[(i*n2 + k)*n3 + n];
                    if (c == 0.0) continue;
                    double ar = sQ1[i*n1 + j][0], ai = sQ1[i*n1 + j][1];
                    double br = sQ2[k*n2 + l][0], bi = sQ2[k*n2 + l][1];
                    double t1r = ar*br - ai*bi, t1i = ar*bi + ai*br;
                    double cr = sQ3[n*n3 + m][0], ci = -sQ3[n*n3 + m][1];
                    double t2r = t1r*cr - t1i*ci, t2i = t1r*ci + t1i*cr;
                    xr += c * t2r; xi += c * t2i;
                }
        sXr[idx] = xr; sXi[idx] = xi;
    }
    __syncthreads();

    if (tid == 0) {
        const int tot = n1*n2*n3;
        double nr = 0.0, ni = 0.0;
        for (int i = 0; i < tot; ++i) { nr += sXr[i]*sXr[i]; ni += sXi[i]*sXi[i]; }
        const double* src = (nr >= ni) ? sXr : sXi;
        double norm = sqrt((nr >= ni) ? nr : ni);
        double fan = (l3 == 0) ? 384.0 : 512.0;
        double scale = sqrt((2.0*l3 + 1.0) / fan) / norm;

        int cnt = 0;
        int icnt[5] = {0,0,0,0,0};
        for (int i = 0; i < n1; ++i)
            for (int jj = 0; jj < n2; ++jj)
                for (int kk = 0; kk < n3; ++kk) {
                    double v = src[(i*n2 + jj)*n3 + kk] * scale;
                    if (fabs(v) > 1e-10) {
                        Ent e; e.v = (float)v; e.i = i; e.j = dSEG2[l2] + jj; e.k = kk;
                        g_ent[p][cnt++] = e;
                        icnt[i]++;
                    }
                }
        for (int i = 0; i < 5; ++i) g_icnt[p][i] = icnt[i];
    }
}

// ---------------------------------------------------------------------------
// f32x2 packed helpers (PTX f32x2, sm_100+)
// ---------------------------------------------------------------------------
__device__ __forceinline__ void lds_2x64(unsigned long long &a, unsigned long long &b,
                                         unsigned addr) {
    asm volatile("ld.shared.v2.u64 {%0,%1},[%2];" : "=l"(a), "=l"(b) : "r"(addr));
}
__device__ __forceinline__ unsigned long long pack2(float x) {
    unsigned long long r;
    asm("mov.b64 %0, {%1,%1};" : "=l"(r) : "f"(x));
    return r;
}
__device__ __forceinline__ void fma2(unsigned long long &acc, unsigned long long a,
                                     unsigned long long b) {
    asm("fma.rn.f32x2 %0, %1, %2, %0;" : "+l"(acc) : "l"(a), "l"(b));
}
__device__ __forceinline__ float2 unpack2(unsigned long long v) {
    float2 f;
    asm("mov.b64 {%0,%1}, %2;" : "=f"(f.x), "=f"(f.y) : "l"(v));
    return f;
}

// ---------------------------------------------------------------------------
// Main kernel: 256 threads, TILE_N=4 rows.
//   stage 1: half h = tid/128 computes t for nn in {2h, 2h+1}
//   stage 2: half 0 -> lo=2 group; half 1 -> lo=0 + lo=1 groups
// ---------------------------------------------------------------------------
__global__ __launch_bounds__(256, 3)
void fctp_kernel(const float* __restrict__ x1,
                 const float* __restrict__ x2,
                 const float* __restrict__ wgt,
                 float* __restrict__ out,
                 int N)
{
    extern __shared__ float sh[];
    float* t_s  = sh;                         // [35][128][4]
    float* x2s  = sh + NKC*128*TILE_N;        // [4][9]

    const int n0 = blockIdx.x * TILE_N;
    if (n0 >= N) return;
    const int tid  = threadIdx.x;
    const int lane = tid & 127;               // u (stage1) / w (stage2)
    const int half = tid >> 7;
    const int nv   = min(TILE_N, N - n0);

    if (tid < TILE_N*9) {
        int r = tid / 9, c = tid % 9;
        int n = min(n0 + r, N - 1);
        x2s[r*9 + c] = x2[n*9 + c];
    }
    __syncthreads();

    // ---------------- Stage 1: t[kc][u][nn], nn split by half -------------
    {
        constexpr int L1[11]  = {0,0,0,1,1,1,1,2,2,2,2};
        constexpr int LO[11]  = {0,1,2,1,0,2,1,2,1,0,2};
        constexpr int TKO[11] = {0,1,4,9,12,13,18,21,26,29,30};
        constexpr int SEG1[3] = {0,128,512};

        const int u = lane;
        for (int nn = 2*half; nn < 2*half + 2; ++nn) {
            const int n = min(n0 + nn, N - 1);
            const float* __restrict__ row = x1 + (long)n * 1152;
            const float* x2r = x2s + nn*9;
            #pragma unroll
            for (int p = 0; p < 11; ++p) {
                const int l1 = L1[p], lo = LO[p];
                const int d1 = 2*l1 + 1, nk = 2*lo + 1, tko = TKO[p];
                const float* base = row + SEG1[l1] + u*d1;
                float acc[5] = {0.f,0.f,0.f,0.f,0.f};
                int eidx = 0;
                #pragma unroll
                for (int i = 0; i < 5; ++i) {
                    if (i < d1) {
                        const float xv = __ldg(base + i);
                        const int ci = g_icnt[p][i];
                        for (int c = 0; c < ci; ++c, ++eidx) {
                            const Ent en = g_ent[p][eidx];
                            const float prod = en.v * xv * x2r[en.j];
                            #pragma unroll
                            for (int kk = 0; kk < 5; ++kk)
                                if (kk < nk) acc[kk] += (en.k == kk) ? prod : 0.0f;
                        }
                    }
                }
                #pragma unroll
                for (int kk = 0; kk < 5; ++kk)
                    if (kk < nk) t_s[(tko + kk)*(128*TILE_N) + u*TILE_N + nn] = acc[kk];
            }
        }
    }
    __syncthreads();

    // ---------------- Stage 2: packed f32x2 reductions --------------------
    const int w = lane;
    const unsigned tbase = (unsigned)__cvta_generic_to_shared(t_s);

    if (half == 0) {
        // lo = 2 : paths 2,5,7,10 (t cols 4,13,21,30), 5 components
        constexpr int PP[4] = {2,5,7,10};
        constexpr int TT[4] = {4,13,21,30};
        unsigned long long acc[5][2] = {};
        #pragma unroll
        for (int pi = 0; pi < 4; ++pi) {
            const float* __restrict__ Wp = wgt + PP[pi]*16384 + w;
            const unsigned ta = tbase + TT[pi]*512*4;
            #pragma unroll 4
            for (int u = 0; u < 128; ++u) {
                unsigned long long wp = pack2(__ldg(Wp + (u << 7)));
                #pragma unroll
                for (int k = 0; k < 5; ++k) {
                    unsigned long long p0, p1;
                    lds_2x64(p0, p1, ta + (unsigned)((k*512 + u*4) * 4));
                    fma2(acc[k][0], p0, wp);
                    fma2(acc[k][1], p1, wp);
                }
            }
        }
        #pragma unroll
        for (int k = 0; k < 5; ++k) {
            float2 lo = unpack2(acc[k][0]);
            float2 hi = unpack2(acc[k][1]);
            float v[4] = {lo.x, lo.y, hi.x, hi.y};
            #pragma unroll
            for (int nn = 0; nn < TILE_N; ++nn)
                if (nn < nv) out[(long)(n0 + nn)*1152 + 512 + w*5 + k] = v[nn];
        }
    } else {
        // lo = 1 : paths 1,3,6,8 (t cols 1,9,18,26), 3 components
        {
            constexpr int PP[4] = {1,3,6,8};
            constexpr int TT[4] = {1,9,18,26};
            unsigned long long acc[3][2] = {};
            #pragma unroll
            for (int pi = 0; pi < 4; ++pi) {
                const float* __restrict__ Wp = wgt + PP[pi]*16384 + w;
                const unsigned ta = tbase + TT[pi]*512*4;
                #pragma unroll 4
                for (int u = 0; u < 128; ++u) {
                    unsigned long long wp = pack2(__ldg(Wp + (u << 7)));
                    #pragma unroll
                    for (int k = 0; k < 3; ++k) {
                        unsigned long long p0, p1;
                        lds_2x64(p0, p1, ta + (unsigned)((k*512 + u*4) * 4));
                        fma2(acc[k][0], p0, wp);
                        fma2(acc[k][1], p1, wp);
                    }
                }
            }
            #pragma unroll
            for (int k = 0; k < 3; ++k) {
                float2 lo = unpack2(acc[k][0]);
                float2 hi = unpack2(acc[k][1]);
                float v[4] = {lo.x, lo.y, hi.x, hi.y};
                #pragma unroll
                for (int nn = 0; nn < TILE_N; ++nn)
                    if (nn < nv) out[(long)(n0 + nn)*1152 + 128 + w*3 + k] = v[nn];
            }
        }
        // lo = 0 : paths 0,4,9 (t cols 0,12,29), 1 component
        {
            constexpr int PP[3] = {0,4,9};
            constexpr int TT[3] = {0,12,29};
            unsigned long long a0 = 0, a1 = 0;
            #pragma unroll
            for (int pi = 0; pi < 3; ++pi) {
                const float* __restrict__ Wp = wgt + PP[pi]*16384 + w;
                const unsigned ta = tbase + TT[pi]*512*4;
                #pragma unroll 8
                for (int u = 0; u < 128; ++u) {
                    unsigned long long wp = pack2(__ldg(Wp + (u << 7)));
                    unsigned long long p0, p1;
                    lds_2x64(p0, p1, ta + (unsigned)(u*16));
                    fma2(a0, p0, wp);
                    fma2(a1, p1, wp);
                }
            }
            float2 lo = unpack2(a0);
            float2 hi = unpack2(a1);
            float v[4] = {lo.x, lo.y, hi.x, hi.y};
            #pragma unroll
            for (int nn = 0; nn < TILE_N; ++nn)
                if (nn < nv) out[(long)(n0 + nn)*1152 + w] = v[nn];
        }
    }
}

// ---------------------------------------------------------------------------
extern "C" void kernel_launch(void* const* d_in, const int* in_sizes, int n_in,
                              void* d_out, int out_size)
{
    const float* x1  = (const float*)d_in[0];
    const float* x2  = (const float*)d_in[1];
    const float* wgt = (const float*)d_in[2];
    float* out = (float*)d_out;

    const int N = in_sizes[0] / 1152;
    if (N <= 0) return;

    const int smem_bytes = (NKC*128*TILE_N + TILE_N*9) * (int)sizeof(float);
    cudaFuncSetAttribute(fctp_kernel, cudaFuncAttributeMaxDynamicSharedMemorySize,
                         smem_bytes);

    w3j_init_kernel<<<NPATH, 128>>>();
    const int grid = (N + TILE_N - 1) / TILE_N;
    fctp_kernel<<<grid, 256, smem_bytes>>>(x1, x2, wgt, out, N);
}